// round 11
// baseline (speedup 1.0000x reference)
#include <cuda_runtime.h>
#include <cuda_fp16.h>
#include <cstdint>

#define NN 4096
#define SCALE 1024.0f
#define INV_S2 (1.0f / (1024.0f * 1024.0f))
#define L2E 1.4426950408889634f

// ---------------- scratch (static device globals; no allocation) ----------------
__device__ __half g_xs16[(size_t)NN * NN];   // softmaxed x * SCALE, fp16
__device__ __half g_ys16[(size_t)NN * NN];   // softmaxed y * SCALE, fp16
__device__ float g_x2[NN];
__device__ float g_y2[NN];
__device__ float g_sum_part[32 * NN];
__device__ float g_w10[NN];                  // (log_nu - L_j) * log2(e)
__device__ float g_cost_part[2048];

// ---------------- PTX helpers ----------------
__device__ __forceinline__ uint32_t smem_u32(const void* p) {
    uint32_t a;
    asm("{ .reg .u64 t; cvta.to.shared.u64 t, %1; cvt.u32.u64 %0, t; }" : "=r"(a) : "l"(p));
    return a;
}

__device__ __forceinline__ float fast_ex2(float x) {
    float r;
    asm("ex2.approx.ftz.f32 %0, %1;" : "=f"(r) : "f"(x));
    return r;
}

__device__ __forceinline__ void cp_async16(uint32_t smem_dst, const void* gmem_src) {
    asm volatile("cp.async.cg.shared.global [%0], [%1], 16;\n" :: "r"(smem_dst), "l"(gmem_src));
}

#define MBAR_INIT(addr, cnt) \
    asm volatile("mbarrier.init.shared.b64 [%0], %1;" :: "r"(addr), "r"(cnt) : "memory")
#define MBAR_ARRIVE(addr) \
    asm volatile("mbarrier.arrive.shared.b64 _, [%0];" :: "r"(addr) : "memory")
#define CP_MBAR_ARRIVE(addr) \
    asm volatile("cp.async.mbarrier.arrive.noinc.shared.b64 [%0];" :: "r"(addr) : "memory")

#define MBAR_WAIT(addr, parity) do {                                              \
    uint32_t _m = (addr); uint32_t _p = (parity); uint32_t _d;                    \
    asm volatile("{\n\t.reg .pred p;\n\t"                                         \
        "mbarrier.try_wait.parity.acquire.cta.shared::cta.b64 p, [%1], %2;\n\t"   \
        "selp.b32 %0, 1, 0, p;\n\t}"                                              \
        : "=r"(_d) : "r"(_m), "r"(_p) : "memory");                                \
    if (!_d) {                                                                    \
        asm volatile("{\n\t.reg .pred P1;\n\t"                                    \
            "WL_%=:\n\t"                                                          \
            "mbarrier.try_wait.parity.acquire.cta.shared::cta.b64 P1, [%0], %1, 0x989680;\n\t" \
            "@P1 bra.uni WD_%=;\n\t"                                              \
            "bra.uni WL_%=;\n\t"                                                  \
            "WD_%=:\n\t}" :: "r"(_m), "r"(_p) : "memory");                        \
    }                                                                             \
} while (0)

#define LDSM_X4(r0, r1, r2, r3, addr) \
    asm volatile("ldmatrix.sync.aligned.m8n8.x4.shared.b16 {%0,%1,%2,%3}, [%4];" \
        : "=r"(r0), "=r"(r1), "=r"(r2), "=r"(r3) : "r"(addr))

#define MMA16816(d, a, b) \
    asm volatile("mma.sync.aligned.m16n8k16.row.col.f32.f16.f16.f32 " \
        "{%0,%1,%2,%3}, {%4,%5,%6,%7}, {%8,%9}, {%0,%1,%2,%3};" \
        : "+f"((d)[0]), "+f"((d)[1]), "+f"((d)[2]), "+f"((d)[3]) \
        : "r"((a)[0]), "r"((a)[1]), "r"((a)[2]), "r"((a)[3]), "r"((b)[0]), "r"((b)[1]))

// ---------------- block reduction ----------------
__device__ __forceinline__ float blockSum256(float v) {
    __shared__ float sm[8];
    int lane = threadIdx.x & 31, w = threadIdx.x >> 5;
    #pragma unroll
    for (int o = 16; o > 0; o >>= 1) v += __shfl_xor_sync(0xffffffffu, v, o);
    if (lane == 0) sm[w] = v;
    __syncthreads();
    if (w == 0) {
        v = (lane < 8) ? sm[lane] : 0.0f;
        #pragma unroll
        for (int o = 4; o > 0; o >>= 1) v += __shfl_xor_sync(0xffffffffu, v, o);
        if (lane == 0) sm[0] = v;
    }
    __syncthreads();
    float r = sm[0];
    __syncthreads();
    return r;
}

// ---------------- 0) dummies: align ncu capture (launch #4 = gemm) ----------------
__global__ void dummy_kernel() {}

// ---------------- 1) row softmax (no max shift: inputs ~N(0,1), fp32 safe) ----------------
__global__ void softmax_kernel(const float* __restrict__ xin, const float* __restrict__ yin) {
    int which = (blockIdx.x >= NN);
    int row = blockIdx.x - which * NN;
    const float* in = which ? yin : xin;
    __half* outp = which ? g_ys16 : g_xs16;
    float* sq    = which ? g_y2 : g_x2;
    const float4* rp = (const float4*)(in + (size_t)row * NN);
    uint2* wp = (uint2*)(outp + (size_t)row * NN);

    float4 v[4];
    #pragma unroll
    for (int i = 0; i < 4; i++) v[i] = __ldcs(&rp[threadIdx.x + i * 256]);

    float s = 0.0f;
    #pragma unroll
    for (int i = 0; i < 4; i++) {
        v[i].x = fast_ex2(v[i].x * L2E);
        v[i].y = fast_ex2(v[i].y * L2E);
        v[i].z = fast_ex2(v[i].z * L2E);
        v[i].w = fast_ex2(v[i].w * L2E);
        s += (v[i].x + v[i].y) + (v[i].z + v[i].w);
    }
    s = blockSum256(s);
    float inv = 1.0f / s;

    float q = 0.0f;
    #pragma unroll
    for (int i = 0; i < 4; i++) {
        float px = v[i].x * inv, py = v[i].y * inv, pz = v[i].z * inv, pw = v[i].w * inv;
        q += px * px + py * py + pz * pz + pw * pw;
        __half2 h0 = __floats2half2_rn(px * SCALE, py * SCALE);
        __half2 h1 = __floats2half2_rn(pz * SCALE, pw * SCALE);
        uint2 o;
        o.x = *(uint32_t*)&h0;
        o.y = *(uint32_t*)&h1;
        wp[threadIdx.x + i * 256] = o;
    }
    q = blockSum256(q);
    if (threadIdx.x == 0) sq[row] = q;
}

// ---------------- 2) fp16 mma.sync GEMM, 128x128 CTA, free-running mbarrier pipeline ----------------
#define BKC 64
#define KT (NN / BKC)          // 64
#define STAGE_BYTES 32768u     // 16KB A + 16KB B
#define SMEM_TOTAL  (3 * STAGE_BYTES)   // 96KB

__global__ __launch_bounds__(256, 2) void gemm_kernel(float* __restrict__ C) {
    extern __shared__ __align__(128) char dyn[];
    __shared__ __align__(8) uint64_t mbar[6];   // [0..2]=full, [3..5]=empty
    __shared__ float part[8][64];
    uint32_t sbase = smem_u32(dyn);

    int tid = threadIdx.x, warp = tid >> 5, lane = tid & 31;

    int bid = blockIdx.x;
    const int TILES = NN / 128;  // 32
    const int GROUP = 8;
    int width = GROUP * TILES;
    int g = bid / width;
    int r = bid % width;
    int bm = g * GROUP + (r % GROUP);
    int bn = r / GROUP;
    int rowBase = bm * 128, colBase = bn * 128;

    int wm = warp >> 1;
    int wn = warp & 1;

    if (tid == 0) {
        #pragma unroll
        for (int i = 0; i < 6; i++) MBAR_INIT(smem_u32(&mbar[i]), 256);
    }
    __syncthreads();

    float acc[2][8][4];
    #pragma unroll
    for (int mt = 0; mt < 2; mt++)
        #pragma unroll
        for (int nt = 0; nt < 8; nt++)
            #pragma unroll
            for (int e = 0; e < 4; e++) acc[mt][nt][e] = 0.0f;

    // per-thread cp.async slice for one chunk (4 A rows-chunks + 4 B)
    int ldrow = tid >> 3;            // base row 0..31 pattern via lin
    (void)ldrow;
    auto produce = [&](int kt) {
        int s = kt % 3;
        MBAR_WAIT(smem_u32(&mbar[3 + s]), ((kt / 3) & 1) ^ 1);
        uint32_t smA = sbase + (uint32_t)s * STAGE_BYTES;
        uint32_t smB = smA + 16384u;
        int k0 = kt * BKC;
        #pragma unroll
        for (int i = 0; i < 4; i++) {
            int lin = tid + i * 256;
            int row = lin >> 3, ch = lin & 7;
            uint32_t phys = (uint32_t)row * 128u + (uint32_t)((ch ^ (row & 7)) << 4);
            cp_async16(smA + phys, (const char*)(g_xs16 + (size_t)(rowBase + row) * NN + k0) + ch * 16);
            cp_async16(smB + phys, (const char*)(g_ys16 + (size_t)(colBase + row) * NN + k0) + ch * 16);
        }
        CP_MBAR_ARRIVE(smem_u32(&mbar[s]));
    };

    produce(0); produce(1); produce(2);

    int aRowSel = (lane & 7) + ((lane >> 3) & 1) * 8;
    int aChSel  = (lane >> 4);
    int bColSel = ((lane >> 4) & 1) * 8 + (lane & 7);
    int bChSel  = (lane >> 3) & 1;

    for (int kt = 0; kt < KT; kt++) {
        int s = kt % 3;
        MBAR_WAIT(smem_u32(&mbar[s]), (kt / 3) & 1);

        uint32_t aBase = sbase + (uint32_t)s * STAGE_BYTES;
        uint32_t bBase = aBase + 16384u;

        #pragma unroll
        for (int kk = 0; kk < 4; kk++) {
            uint32_t a[2][4];
            #pragma unroll
            for (int mt = 0; mt < 2; mt++) {
                int rowL = wm * 32 + mt * 16 + aRowSel;
                int ch = 2 * kk + aChSel;
                uint32_t addr = aBase + (uint32_t)rowL * 128u + (uint32_t)((ch ^ (rowL & 7)) << 4);
                LDSM_X4(a[mt][0], a[mt][1], a[mt][2], a[mt][3], addr);
            }
            uint32_t b[8][2];
            #pragma unroll
            for (int np = 0; np < 4; np++) {
                int colL = wn * 64 + np * 16 + bColSel;
                int ch = 2 * kk + bChSel;
                uint32_t addr = bBase + (uint32_t)colL * 128u + (uint32_t)((ch ^ (colL & 7)) << 4);
                uint32_t r0, r1, r2, r3;
                LDSM_X4(r0, r1, r2, r3, addr);
                b[2 * np][0] = r0; b[2 * np][1] = r1;
                b[2 * np + 1][0] = r2; b[2 * np + 1][1] = r3;
            }
            #pragma unroll
            for (int mt = 0; mt < 2; mt++)
                #pragma unroll
                for (int nt = 0; nt < 8; nt++)
                    MMA16816(acc[mt][nt], a[mt], b[nt]);
        }

        MBAR_ARRIVE(smem_u32(&mbar[3 + s]));
        if (kt + 3 < KT) produce(kt + 3);
    }
    __syncthreads();   // all consumes done before smem reuse by epilogue staging

    // ---------------- epilogue: C = x2+y2-2G, fused column-sums of exp(-10C) ----------------
    float* stg = (float*)dyn + warp * (32 * 66);
    int rsel = lane >> 2, csel = (lane & 3) * 2;
    #pragma unroll
    for (int mt = 0; mt < 2; mt++) {
        #pragma unroll
        for (int nt = 0; nt < 8; nt++) {
            stg[(mt * 16 + rsel) * 66 + nt * 8 + csel]     = acc[mt][nt][0];
            stg[(mt * 16 + rsel) * 66 + nt * 8 + csel + 1] = acc[mt][nt][1];
            stg[(mt * 16 + rsel + 8) * 66 + nt * 8 + csel]     = acc[mt][nt][2];
            stg[(mt * 16 + rsel + 8) * 66 + nt * 8 + csel + 1] = acc[mt][nt][3];
        }
    }
    __syncwarp();

    int growBase = rowBase + wm * 32;
    int gcol = colBase + wn * 64 + 2 * lane;
    float y0 = g_y2[gcol], y1 = g_y2[gcol + 1];
    float sexp0 = 0.0f, sexp1 = 0.0f;
    const float NEG10L2E = -10.0f * L2E;
    #pragma unroll 4
    for (int rr = 0; rr < 32; rr++) {
        int grow = growBase + rr;
        float xv = g_x2[grow];
        float v0 = xv + y0 - 2.0f * INV_S2 * stg[rr * 66 + 2 * lane];
        float v1 = xv + y1 - 2.0f * INV_S2 * stg[rr * 66 + 2 * lane + 1];
        float* cp = C + (size_t)grow * NN + gcol;
        cp[0] = v0;
        cp[1] = v1;
        sexp0 += fast_ex2(NEG10L2E * v0);
        sexp1 += fast_ex2(NEG10L2E * v1);
    }
    part[warp][2 * lane]     = sexp0;
    part[warp][2 * lane + 1] = sexp1;
    __syncthreads();
    if (tid < 128) {
        int wnq = tid >> 6, cl = tid & 63;
        float s = part[wnq][cl] + part[2 + wnq][cl] + part[4 + wnq][cl] + part[6 + wnq][cl];
        g_sum_part[(size_t)bm * NN + colBase + wnq * 64 + cl] = s;
    }
}

// ---------------- 3) combine column sums -> w (log2 domain) ----------------
__global__ void combine_sum_kernel() {
    int col = blockIdx.x * 256 + threadIdx.x;
    float S = 0.0f;
    #pragma unroll
    for (int i = 0; i < 32; i++) S += g_sum_part[(size_t)i * NN + col];
    float log_nu = logf(1.0f / 4096.0f + 1e-8f);
    g_w10[col] = (log_nu - logf(S)) * L2E;
}

// ---------------- 4) pi = exp2(-10*L2E*C + w2[j]); cost = sum(pi*C); 2 rows/block, streaming ----------------
__global__ void pi_cost_kernel(const float* __restrict__ C, float* __restrict__ pi) {
    __shared__ float w[NN];
    int row0 = blockIdx.x * 2;
    for (int i = threadIdx.x; i < NN; i += 256) w[i] = g_w10[i];
    __syncthreads();

    const float NEG10L2E = -10.0f * L2E;
    const float* cr0 = C + (size_t)row0 * NN;
    const float* cr1 = cr0 + NN;
    float* pr0 = pi + (size_t)row0 * NN;
    float* pr1 = pr0 + NN;

    float lc = 0.0f;
    #pragma unroll
    for (int i = 0; i < 16; i++) {
        int j = threadIdx.x + i * 256;
        float c0 = __ldcs(cr0 + j);
        float c1 = __ldcs(cr1 + j);
        float wj = w[j];
        float p0 = fast_ex2(fmaf(NEG10L2E, c0, wj));
        float p1 = fast_ex2(fmaf(NEG10L2E, c1, wj));
        __stcs(pr0 + j, p0);
        __stcs(pr1 + j, p1);
        lc = fmaf(p0, c0, lc);
        lc = fmaf(p1, c1, lc);
    }
    lc = blockSum256(lc);
    if (threadIdx.x == 0) g_cost_part[blockIdx.x] = lc;
}

__global__ void cost_final_kernel(float* __restrict__ out) {
    float s = 0.0f;
    for (int i = threadIdx.x; i < 2048; i += 256) s += g_cost_part[i];
    s = blockSum256(s);
    if (threadIdx.x == 0) out[0] = s;
}

// ---------------- launch ----------------
extern "C" void kernel_launch(void* const* d_in, const int* in_sizes, int n_in,
                              void* d_out, int out_size) {
    const float* x = (const float*)d_in[0];
    const float* y = (const float*)d_in[1];
    float* out = (float*)d_out;
    float* pi = out + 1;                        // [N*N]
    float* C  = out + 1 + (size_t)NN * NN;      // [N*N]

    cudaFuncSetAttribute(gemm_kernel, cudaFuncAttributeMaxDynamicSharedMemorySize, SMEM_TOTAL);

    dummy_kernel<<<1, 32>>>();                  // ncu alignment: launch #4 = gemm
    dummy_kernel<<<1, 32>>>();

    softmax_kernel<<<2 * NN, 256>>>(x, y);

    gemm_kernel<<<(NN / 128) * (NN / 128), 256, SMEM_TOTAL>>>(C);

    combine_sum_kernel<<<NN / 256, 256>>>();

    pi_cost_kernel<<<2048, 256>>>(C, pi);
    cost_final_kernel<<<1, 256>>>(out);
}

// round 12
// speedup vs baseline: 1.3968x; 1.3968x over previous
#include <cuda_runtime.h>
#include <cuda_fp16.h>
#include <cstdint>

#define NN 4096
#define SCALE 1024.0f
#define INV_S2 (1.0f / (1024.0f * 1024.0f))
#define L2E 1.4426950408889634f

// ---------------- scratch (static device globals; no allocation) ----------------
__device__ __half g_xs16[(size_t)NN * NN];   // softmaxed x * SCALE, fp16
__device__ __half g_ys16[(size_t)NN * NN];   // softmaxed y * SCALE, fp16
__device__ float g_x2[NN];
__device__ float g_y2[NN];
__device__ float g_sum_part[32 * NN];
__device__ float g_w10[NN];                  // (log_nu - L_j) * log2(e)
__device__ float g_cost_part[2048];

// ---------------- PTX helpers ----------------
__device__ __forceinline__ uint32_t smem_u32(const void* p) {
    uint32_t a;
    asm("{ .reg .u64 t; cvta.to.shared.u64 t, %1; cvt.u32.u64 %0, t; }" : "=r"(a) : "l"(p));
    return a;
}

__device__ __forceinline__ float fast_ex2(float x) {
    float r;
    asm("ex2.approx.ftz.f32 %0, %1;" : "=f"(r) : "f"(x));
    return r;
}

__device__ __forceinline__ void cp_async16(uint32_t smem_dst, const void* gmem_src) {
    asm volatile("cp.async.cg.shared.global [%0], [%1], 16;\n" :: "r"(smem_dst), "l"(gmem_src));
}
#define CP_COMMIT() asm volatile("cp.async.commit_group;\n" ::: "memory")
#define CP_WAIT1()  asm volatile("cp.async.wait_group 1;\n" ::: "memory")
#define CP_WAIT0()  asm volatile("cp.async.wait_group 0;\n" ::: "memory")

#define LDSM_X4(r0, r1, r2, r3, addr) \
    asm volatile("ldmatrix.sync.aligned.m8n8.x4.shared.b16 {%0,%1,%2,%3}, [%4];" \
        : "=r"(r0), "=r"(r1), "=r"(r2), "=r"(r3) : "r"(addr))

#define MMA16816(d, a, b) \
    asm volatile("mma.sync.aligned.m16n8k16.row.col.f32.f16.f16.f32 " \
        "{%0,%1,%2,%3}, {%4,%5,%6,%7}, {%8,%9}, {%0,%1,%2,%3};" \
        : "+f"((d)[0]), "+f"((d)[1]), "+f"((d)[2]), "+f"((d)[3]) \
        : "r"((a)[0]), "r"((a)[1]), "r"((a)[2]), "r"((a)[3]), "r"((b)[0]), "r"((b)[1]))

// ---------------- block reduction ----------------
__device__ __forceinline__ float blockSum256(float v) {
    __shared__ float sm[8];
    int lane = threadIdx.x & 31, w = threadIdx.x >> 5;
    #pragma unroll
    for (int o = 16; o > 0; o >>= 1) v += __shfl_xor_sync(0xffffffffu, v, o);
    if (lane == 0) sm[w] = v;
    __syncthreads();
    if (w == 0) {
        v = (lane < 8) ? sm[lane] : 0.0f;
        #pragma unroll
        for (int o = 4; o > 0; o >>= 1) v += __shfl_xor_sync(0xffffffffu, v, o);
        if (lane == 0) sm[0] = v;
    }
    __syncthreads();
    float r = sm[0];
    __syncthreads();
    return r;
}

// ---------------- 1) row softmax (no max shift: inputs ~N(0,1), fp32 safe) ----------------
__global__ void softmax_kernel(const float* __restrict__ xin, const float* __restrict__ yin) {
    int which = (blockIdx.x >= NN);
    int row = blockIdx.x - which * NN;
    const float* in = which ? yin : xin;
    __half* outp = which ? g_ys16 : g_xs16;
    float* sq    = which ? g_y2 : g_x2;
    const float4* rp = (const float4*)(in + (size_t)row * NN);
    uint2* wp = (uint2*)(outp + (size_t)row * NN);

    float4 v[4];
    #pragma unroll
    for (int i = 0; i < 4; i++) v[i] = __ldcs(&rp[threadIdx.x + i * 256]);

    float s = 0.0f;
    #pragma unroll
    for (int i = 0; i < 4; i++) {
        v[i].x = fast_ex2(v[i].x * L2E);
        v[i].y = fast_ex2(v[i].y * L2E);
        v[i].z = fast_ex2(v[i].z * L2E);
        v[i].w = fast_ex2(v[i].w * L2E);
        s += (v[i].x + v[i].y) + (v[i].z + v[i].w);
    }
    s = blockSum256(s);
    float inv = 1.0f / s;

    float q = 0.0f;
    #pragma unroll
    for (int i = 0; i < 4; i++) {
        float px = v[i].x * inv, py = v[i].y * inv, pz = v[i].z * inv, pw = v[i].w * inv;
        q += px * px + py * py + pz * pz + pw * pw;
        __half2 h0 = __floats2half2_rn(px * SCALE, py * SCALE);
        __half2 h1 = __floats2half2_rn(pz * SCALE, pw * SCALE);
        uint2 o;
        o.x = *(uint32_t*)&h0;
        o.y = *(uint32_t*)&h1;
        wp[threadIdx.x + i * 256] = o;
    }
    q = blockSum256(q);
    if (threadIdx.x == 0) sq[row] = q;
}

// ---------------- 2) fp16 mma.sync GEMM, 128x128 CTA tile, 32x64 warp tile (R6 proven) ----------------
#define BKC 64
#define KT (NN / BKC)          // 64
#define STAGE_BYTES 32768u     // 16KB A + 16KB B
#define SMEM_TOTAL  (3 * STAGE_BYTES)   // 96KB

__global__ __launch_bounds__(256, 2) void gemm_kernel(float* __restrict__ C) {
    extern __shared__ __align__(128) char dyn[];
    __shared__ float part[8][64];
    uint32_t sbase = smem_u32(dyn);

    int tid = threadIdx.x, warp = tid >> 5, lane = tid & 31;

    int bid = blockIdx.x;
    const int TILES = NN / 128;  // 32
    const int GROUP = 8;
    int width = GROUP * TILES;
    int g = bid / width;
    int r = bid % width;
    int bm = g * GROUP + (r % GROUP);
    int bn = r / GROUP;
    int rowBase = bm * 128, colBase = bn * 128;

    int wm = warp >> 1;
    int wn = warp & 1;

    float acc[2][8][4];
    #pragma unroll
    for (int mt = 0; mt < 2; mt++)
        #pragma unroll
        for (int nt = 0; nt < 8; nt++)
            #pragma unroll
            for (int e = 0; e < 4; e++) acc[mt][nt][e] = 0.0f;

    auto issue = [&](int s, int kt) {
        uint32_t smA = sbase + (uint32_t)s * STAGE_BYTES;
        uint32_t smB = smA + 16384u;
        int k0 = kt * BKC;
        #pragma unroll
        for (int i = 0; i < 4; i++) {
            int lin = tid + i * 256;
            int row = lin >> 3, ch = lin & 7;
            uint32_t phys = (uint32_t)row * 128u + (uint32_t)((ch ^ (row & 7)) << 4);
            cp_async16(smA + phys, (const char*)(g_xs16 + (size_t)(rowBase + row) * NN + k0) + ch * 16);
            cp_async16(smB + phys, (const char*)(g_ys16 + (size_t)(colBase + row) * NN + k0) + ch * 16);
        }
        CP_COMMIT();
    };

    issue(0, 0);
    issue(1, 1);

    int aRowSel = (lane & 7) + ((lane >> 3) & 1) * 8;
    int aChSel  = (lane >> 4);
    int bColSel = ((lane >> 4) & 1) * 8 + (lane & 7);
    int bChSel  = (lane >> 3) & 1;

    for (int kt = 0; kt < KT; kt++) {
        if (kt == KT - 1) { CP_WAIT0(); } else { CP_WAIT1(); }
        __syncthreads();
        if (kt + 2 < KT) issue((kt + 2) % 3, kt + 2);

        uint32_t aBase = sbase + (uint32_t)(kt % 3) * STAGE_BYTES;
        uint32_t bBase = aBase + 16384u;

        #pragma unroll
        for (int kk = 0; kk < 4; kk++) {
            uint32_t a[2][4];
            #pragma unroll
            for (int mt = 0; mt < 2; mt++) {
                int rowL = wm * 32 + mt * 16 + aRowSel;
                int ch = 2 * kk + aChSel;
                uint32_t addr = aBase + (uint32_t)rowL * 128u + (uint32_t)((ch ^ (rowL & 7)) << 4);
                LDSM_X4(a[mt][0], a[mt][1], a[mt][2], a[mt][3], addr);
            }
            uint32_t b[8][2];
            #pragma unroll
            for (int np = 0; np < 4; np++) {
                int colL = wn * 64 + np * 16 + bColSel;
                int ch = 2 * kk + bChSel;
                uint32_t addr = bBase + (uint32_t)colL * 128u + (uint32_t)((ch ^ (colL & 7)) << 4);
                uint32_t r0, r1, r2, r3;
                LDSM_X4(r0, r1, r2, r3, addr);
                b[2 * np][0] = r0; b[2 * np][1] = r1;
                b[2 * np + 1][0] = r2; b[2 * np + 1][1] = r3;
            }
            #pragma unroll
            for (int mt = 0; mt < 2; mt++)
                #pragma unroll
                for (int nt = 0; nt < 8; nt++)
                    MMA16816(acc[mt][nt], a[mt], b[nt]);
        }
    }
    __syncthreads();   // protect smem reuse by epilogue staging

    // ---------------- epilogue: C = x2+y2-2G, fused column-sums of exp(-10C) ----------------
    float* stg = (float*)dyn + warp * (32 * 66);
    int rsel = lane >> 2, csel = (lane & 3) * 2;
    #pragma unroll
    for (int mt = 0; mt < 2; mt++) {
        #pragma unroll
        for (int nt = 0; nt < 8; nt++) {
            stg[(mt * 16 + rsel) * 66 + nt * 8 + csel]     = acc[mt][nt][0];
            stg[(mt * 16 + rsel) * 66 + nt * 8 + csel + 1] = acc[mt][nt][1];
            stg[(mt * 16 + rsel + 8) * 66 + nt * 8 + csel]     = acc[mt][nt][2];
            stg[(mt * 16 + rsel + 8) * 66 + nt * 8 + csel + 1] = acc[mt][nt][3];
        }
    }
    __syncwarp();

    int growBase = rowBase + wm * 32;
    int gcol = colBase + wn * 64 + 2 * lane;
    float y0 = g_y2[gcol], y1 = g_y2[gcol + 1];
    float sexp0 = 0.0f, sexp1 = 0.0f;
    const float NEG10L2E = -10.0f * L2E;
    #pragma unroll 4
    for (int rr = 0; rr < 32; rr++) {
        int grow = growBase + rr;
        float xv = g_x2[grow];
        float v0 = xv + y0 - 2.0f * INV_S2 * stg[rr * 66 + 2 * lane];
        float v1 = xv + y1 - 2.0f * INV_S2 * stg[rr * 66 + 2 * lane + 1];
        float* cp = C + (size_t)grow * NN + gcol;
        cp[0] = v0;
        cp[1] = v1;
        sexp0 += fast_ex2(NEG10L2E * v0);
        sexp1 += fast_ex2(NEG10L2E * v1);
    }
    part[warp][2 * lane]     = sexp0;
    part[warp][2 * lane + 1] = sexp1;
    __syncthreads();
    if (tid < 128) {
        int wnq = tid >> 6, cl = tid & 63;
        float s = part[wnq][cl] + part[2 + wnq][cl] + part[4 + wnq][cl] + part[6 + wnq][cl];
        g_sum_part[(size_t)bm * NN + colBase + wnq * 64 + cl] = s;
    }
}

// ---------------- 3) combine column sums -> w (log2 domain) ----------------
__global__ void combine_sum_kernel() {
    int col = blockIdx.x * 256 + threadIdx.x;
    float S = 0.0f;
    #pragma unroll
    for (int i = 0; i < 32; i++) S += g_sum_part[(size_t)i * NN + col];
    float log_nu = logf(1.0f / 4096.0f + 1e-8f);
    g_w10[col] = (log_nu - logf(S)) * L2E;
}

// ---------------- 4) pi = exp2(-10*L2E*C + w2[j]); cost = sum(pi*C); 2 rows/block, streaming ----------------
__global__ void pi_cost_kernel(const float* __restrict__ C, float* __restrict__ pi) {
    __shared__ float w[NN];
    int row0 = blockIdx.x * 2;
    for (int i = threadIdx.x; i < NN; i += 256) w[i] = g_w10[i];
    __syncthreads();

    const float NEG10L2E = -10.0f * L2E;
    const float* cr0 = C + (size_t)row0 * NN;
    const float* cr1 = cr0 + NN;
    float* pr0 = pi + (size_t)row0 * NN;
    float* pr1 = pr0 + NN;

    float lc = 0.0f;
    #pragma unroll
    for (int i = 0; i < 16; i++) {
        int j = threadIdx.x + i * 256;
        float c0 = __ldcs(cr0 + j);
        float c1 = __ldcs(cr1 + j);
        float wj = w[j];
        float p0 = fast_ex2(fmaf(NEG10L2E, c0, wj));
        float p1 = fast_ex2(fmaf(NEG10L2E, c1, wj));
        __stcs(pr0 + j, p0);
        __stcs(pr1 + j, p1);
        lc = fmaf(p0, c0, lc);
        lc = fmaf(p1, c1, lc);
    }
    lc = blockSum256(lc);
    if (threadIdx.x == 0) g_cost_part[blockIdx.x] = lc;
}

__global__ void cost_final_kernel(float* __restrict__ out) {
    float s = 0.0f;
    for (int i = threadIdx.x; i < 2048; i += 256) s += g_cost_part[i];
    s = blockSum256(s);
    if (threadIdx.x == 0) out[0] = s;
}

// ---------------- launch ----------------
extern "C" void kernel_launch(void* const* d_in, const int* in_sizes, int n_in,
                              void* d_out, int out_size) {
    const float* x = (const float*)d_in[0];
    const float* y = (const float*)d_in[1];
    float* out = (float*)d_out;
    float* pi = out + 1;                        // [N*N]
    float* C  = out + 1 + (size_t)NN * NN;      // [N*N]

    cudaFuncSetAttribute(gemm_kernel, cudaFuncAttributeMaxDynamicSharedMemorySize, SMEM_TOTAL);

    softmax_kernel<<<2 * NN, 256>>>(x, y);

    gemm_kernel<<<(NN / 128) * (NN / 128), 256, SMEM_TOTAL>>>(C);

    combine_sum_kernel<<<NN / 256, 256>>>();

    pi_cost_kernel<<<2048, 256>>>(C, pi);
    cost_final_kernel<<<1, 256>>>(out);
}

// round 13
// speedup vs baseline: 1.4310x; 1.0244x over previous
#include <cuda_runtime.h>
#include <cuda_fp16.h>
#include <cstdint>

#define NN 4096
#define SCALE 1024.0f
#define INV_S2 (1.0f / (1024.0f * 1024.0f))
#define L2E 1.4426950408889634f

// ---------------- scratch (static device globals; no allocation) ----------------
__device__ __half g_xs16[(size_t)NN * NN];   // softmaxed x * SCALE, fp16
__device__ __half g_ys16[(size_t)NN * NN];   // softmaxed y * SCALE, fp16
__device__ float g_x2[NN];
__device__ float g_y2[NN];
__device__ float g_sum_part[32 * NN];
__device__ float g_w10[NN];                  // (log_nu - L_j) * log2(e)
__device__ float g_cost_part[1024];

// ---------------- PTX helpers ----------------
__device__ __forceinline__ uint32_t smem_u32(const void* p) {
    uint32_t a;
    asm("{ .reg .u64 t; cvta.to.shared.u64 t, %1; cvt.u32.u64 %0, t; }" : "=r"(a) : "l"(p));
    return a;
}

__device__ __forceinline__ float fast_ex2(float x) {
    float r;
    asm("ex2.approx.ftz.f32 %0, %1;" : "=f"(r) : "f"(x));
    return r;
}

__device__ __forceinline__ void cp_async16(uint32_t smem_dst, const void* gmem_src) {
    asm volatile("cp.async.cg.shared.global [%0], [%1], 16;\n" :: "r"(smem_dst), "l"(gmem_src));
}
#define CP_COMMIT() asm volatile("cp.async.commit_group;\n" ::: "memory")
#define CP_WAIT1()  asm volatile("cp.async.wait_group 1;\n" ::: "memory")
#define CP_WAIT0()  asm volatile("cp.async.wait_group 0;\n" ::: "memory")

#define LDSM_X4(r0, r1, r2, r3, addr) \
    asm volatile("ldmatrix.sync.aligned.m8n8.x4.shared.b16 {%0,%1,%2,%3}, [%4];" \
        : "=r"(r0), "=r"(r1), "=r"(r2), "=r"(r3) : "r"(addr))

#define MMA16816(d, a, b) \
    asm volatile("mma.sync.aligned.m16n8k16.row.col.f32.f16.f16.f32 " \
        "{%0,%1,%2,%3}, {%4,%5,%6,%7}, {%8,%9}, {%0,%1,%2,%3};" \
        : "+f"((d)[0]), "+f"((d)[1]), "+f"((d)[2]), "+f"((d)[3]) \
        : "r"((a)[0]), "r"((a)[1]), "r"((a)[2]), "r"((a)[3]), "r"((b)[0]), "r"((b)[1]))

// ---------------- block reduction ----------------
__device__ __forceinline__ float blockSum256(float v) {
    __shared__ float sm[8];
    int lane = threadIdx.x & 31, w = threadIdx.x >> 5;
    #pragma unroll
    for (int o = 16; o > 0; o >>= 1) v += __shfl_xor_sync(0xffffffffu, v, o);
    if (lane == 0) sm[w] = v;
    __syncthreads();
    if (w == 0) {
        v = (lane < 8) ? sm[lane] : 0.0f;
        #pragma unroll
        for (int o = 4; o > 0; o >>= 1) v += __shfl_xor_sync(0xffffffffu, v, o);
        if (lane == 0) sm[0] = v;
    }
    __syncthreads();
    float r = sm[0];
    __syncthreads();
    return r;
}

// ---------------- 1) row softmax (no max shift: inputs ~N(0,1), fp32 safe) ----------------
__global__ void softmax_kernel(const float* __restrict__ xin, const float* __restrict__ yin) {
    int which = (blockIdx.x >= NN);
    int row = blockIdx.x - which * NN;
    const float* in = which ? yin : xin;
    __half* outp = which ? g_ys16 : g_xs16;
    float* sq    = which ? g_y2 : g_x2;
    const float4* rp = (const float4*)(in + (size_t)row * NN);
    uint2* wp = (uint2*)(outp + (size_t)row * NN);

    float4 v[4];
    #pragma unroll
    for (int i = 0; i < 4; i++) v[i] = __ldcs(&rp[threadIdx.x + i * 256]);

    float s = 0.0f;
    #pragma unroll
    for (int i = 0; i < 4; i++) {
        v[i].x = fast_ex2(v[i].x * L2E);
        v[i].y = fast_ex2(v[i].y * L2E);
        v[i].z = fast_ex2(v[i].z * L2E);
        v[i].w = fast_ex2(v[i].w * L2E);
        s += (v[i].x + v[i].y) + (v[i].z + v[i].w);
    }
    s = blockSum256(s);
    float inv = 1.0f / s;

    float q = 0.0f;
    #pragma unroll
    for (int i = 0; i < 4; i++) {
        float px = v[i].x * inv, py = v[i].y * inv, pz = v[i].z * inv, pw = v[i].w * inv;
        q += px * px + py * py + pz * pz + pw * pw;
        __half2 h0 = __floats2half2_rn(px * SCALE, py * SCALE);
        __half2 h1 = __floats2half2_rn(pz * SCALE, pw * SCALE);
        uint2 o;
        o.x = *(uint32_t*)&h0;
        o.y = *(uint32_t*)&h1;
        wp[threadIdx.x + i * 256] = o;
    }
    q = blockSum256(q);
    if (threadIdx.x == 0) sq[row] = q;
}

// ---------------- 2) fp16 mma.sync GEMM, 128x128 CTA tile, 32x64 warp tile (R6 proven) ----------------
#define BKC 64
#define KT (NN / BKC)          // 64
#define STAGE_BYTES 32768u     // 16KB A + 16KB B
#define SMEM_TOTAL  (3 * STAGE_BYTES)   // 96KB

__global__ __launch_bounds__(256, 2) void gemm_kernel(float* __restrict__ C) {
    extern __shared__ __align__(128) char dyn[];
    __shared__ float part[8][64];
    uint32_t sbase = smem_u32(dyn);

    int tid = threadIdx.x, warp = tid >> 5, lane = tid & 31;

    int bid = blockIdx.x;
    const int TILES = NN / 128;  // 32
    const int GROUP = 8;
    int width = GROUP * TILES;
    int g = bid / width;
    int r = bid % width;
    int bm = g * GROUP + (r % GROUP);
    int bn = r / GROUP;
    int rowBase = bm * 128, colBase = bn * 128;

    int wm = warp >> 1;
    int wn = warp & 1;

    float acc[2][8][4];
    #pragma unroll
    for (int mt = 0; mt < 2; mt++)
        #pragma unroll
        for (int nt = 0; nt < 8; nt++)
            #pragma unroll
            for (int e = 0; e < 4; e++) acc[mt][nt][e] = 0.0f;

    auto issue = [&](int s, int kt) {
        uint32_t smA = sbase + (uint32_t)s * STAGE_BYTES;
        uint32_t smB = smA + 16384u;
        int k0 = kt * BKC;
        #pragma unroll
        for (int i = 0; i < 4; i++) {
            int lin = tid + i * 256;
            int row = lin >> 3, ch = lin & 7;
            uint32_t phys = (uint32_t)row * 128u + (uint32_t)((ch ^ (row & 7)) << 4);
            cp_async16(smA + phys, (const char*)(g_xs16 + (size_t)(rowBase + row) * NN + k0) + ch * 16);
            cp_async16(smB + phys, (const char*)(g_ys16 + (size_t)(colBase + row) * NN + k0) + ch * 16);
        }
        CP_COMMIT();
    };

    issue(0, 0);
    issue(1, 1);

    int aRowSel = (lane & 7) + ((lane >> 3) & 1) * 8;
    int aChSel  = (lane >> 4);
    int bColSel = ((lane >> 4) & 1) * 8 + (lane & 7);
    int bChSel  = (lane >> 3) & 1;

    for (int kt = 0; kt < KT; kt++) {
        if (kt == KT - 1) { CP_WAIT0(); } else { CP_WAIT1(); }
        __syncthreads();
        if (kt + 2 < KT) issue((kt + 2) % 3, kt + 2);

        uint32_t aBase = sbase + (uint32_t)(kt % 3) * STAGE_BYTES;
        uint32_t bBase = aBase + 16384u;

        #pragma unroll
        for (int kk = 0; kk < 4; kk++) {
            uint32_t a[2][4];
            #pragma unroll
            for (int mt = 0; mt < 2; mt++) {
                int rowL = wm * 32 + mt * 16 + aRowSel;
                int ch = 2 * kk + aChSel;
                uint32_t addr = aBase + (uint32_t)rowL * 128u + (uint32_t)((ch ^ (rowL & 7)) << 4);
                LDSM_X4(a[mt][0], a[mt][1], a[mt][2], a[mt][3], addr);
            }
            uint32_t b[8][2];
            #pragma unroll
            for (int np = 0; np < 4; np++) {
                int colL = wn * 64 + np * 16 + bColSel;
                int ch = 2 * kk + bChSel;
                uint32_t addr = bBase + (uint32_t)colL * 128u + (uint32_t)((ch ^ (colL & 7)) << 4);
                uint32_t r0, r1, r2, r3;
                LDSM_X4(r0, r1, r2, r3, addr);
                b[2 * np][0] = r0; b[2 * np][1] = r1;
                b[2 * np + 1][0] = r2; b[2 * np + 1][1] = r3;
            }
            #pragma unroll
            for (int mt = 0; mt < 2; mt++)
                #pragma unroll
                for (int nt = 0; nt < 8; nt++)
                    MMA16816(acc[mt][nt], a[mt], b[nt]);
        }
    }
    __syncthreads();   // protect smem reuse by epilogue staging

    // ---------------- epilogue: C = x2+y2-2G, fused column-sums of exp(-10C) ----------------
    float* stg = (float*)dyn + warp * (32 * 66);
    int rsel = lane >> 2, csel = (lane & 3) * 2;
    #pragma unroll
    for (int mt = 0; mt < 2; mt++) {
        #pragma unroll
        for (int nt = 0; nt < 8; nt++) {
            stg[(mt * 16 + rsel) * 66 + nt * 8 + csel]     = acc[mt][nt][0];
            stg[(mt * 16 + rsel) * 66 + nt * 8 + csel + 1] = acc[mt][nt][1];
            stg[(mt * 16 + rsel + 8) * 66 + nt * 8 + csel]     = acc[mt][nt][2];
            stg[(mt * 16 + rsel + 8) * 66 + nt * 8 + csel + 1] = acc[mt][nt][3];
        }
    }
    __syncwarp();

    int growBase = rowBase + wm * 32;
    int gcol = colBase + wn * 64 + 2 * lane;
    float y0 = g_y2[gcol], y1 = g_y2[gcol + 1];
    float sexp0 = 0.0f, sexp1 = 0.0f;
    const float NEG10L2E = -10.0f * L2E;
    #pragma unroll 4
    for (int rr = 0; rr < 32; rr++) {
        int grow = growBase + rr;
        float xv = g_x2[grow];
        float v0 = xv + y0 - 2.0f * INV_S2 * stg[rr * 66 + 2 * lane];
        float v1 = xv + y1 - 2.0f * INV_S2 * stg[rr * 66 + 2 * lane + 1];
        float* cp = C + (size_t)grow * NN + gcol;
        cp[0] = v0;
        cp[1] = v1;
        sexp0 += fast_ex2(NEG10L2E * v0);
        sexp1 += fast_ex2(NEG10L2E * v1);
    }
    part[warp][2 * lane]     = sexp0;
    part[warp][2 * lane + 1] = sexp1;
    __syncthreads();
    if (tid < 128) {
        int wnq = tid >> 6, cl = tid & 63;
        float s = part[wnq][cl] + part[2 + wnq][cl] + part[4 + wnq][cl] + part[6 + wnq][cl];
        g_sum_part[(size_t)bm * NN + colBase + wnq * 64 + cl] = s;
    }
}

// ---------------- 3) combine column sums -> w (log2 domain) ----------------
__global__ void combine_sum_kernel() {
    int col = blockIdx.x * 256 + threadIdx.x;
    float S = 0.0f;
    #pragma unroll
    for (int i = 0; i < 32; i++) S += g_sum_part[(size_t)i * NN + col];
    float log_nu = logf(1.0f / 4096.0f + 1e-8f);
    g_w10[col] = (log_nu - logf(S)) * L2E;
}

// ---------------- 4) pi = exp2(-10*L2E*C + w2[j]); cost = sum(pi*C); 4 rows/block (R6 shape) ----------------
__global__ void pi_cost_kernel(const float* __restrict__ C, float* __restrict__ pi) {
    __shared__ float w[NN];
    int row0 = blockIdx.x * 4;
    for (int i = threadIdx.x; i < NN; i += 256) w[i] = g_w10[i];
    __syncthreads();

    const float NEG10L2E = -10.0f * L2E;
    float lc = 0.0f;
    #pragma unroll
    for (int rr = 0; rr < 4; rr++) {
        const float* cr = C + (size_t)(row0 + rr) * NN;
        float* pr = pi + (size_t)(row0 + rr) * NN;
        #pragma unroll
        for (int i = 0; i < 16; i++) {
            int j = threadIdx.x + i * 256;
            float c = cr[j];
            float p = fast_ex2(fmaf(NEG10L2E, c, w[j]));
            pr[j] = p;
            lc = fmaf(p, c, lc);
        }
    }
    lc = blockSum256(lc);
    if (threadIdx.x == 0) g_cost_part[blockIdx.x] = lc;
}

__global__ void cost_final_kernel(float* __restrict__ out) {
    float s = 0.0f;
    for (int i = threadIdx.x; i < 1024; i += 256) s += g_cost_part[i];
    s = blockSum256(s);
    if (threadIdx.x == 0) out[0] = s;
}

// ---------------- launch ----------------
extern "C" void kernel_launch(void* const* d_in, const int* in_sizes, int n_in,
                              void* d_out, int out_size) {
    const float* x = (const float*)d_in[0];
    const float* y = (const float*)d_in[1];
    float* out = (float*)d_out;
    float* pi = out + 1;                        // [N*N]
    float* C  = out + 1 + (size_t)NN * NN;      // [N*N]

    cudaFuncSetAttribute(gemm_kernel, cudaFuncAttributeMaxDynamicSharedMemorySize, SMEM_TOTAL);

    softmax_kernel<<<2 * NN, 256>>>(x, y);

    gemm_kernel<<<(NN / 128) * (NN / 128), 256, SMEM_TOTAL>>>(C);

    combine_sum_kernel<<<NN / 256, 256>>>();

    pi_cost_kernel<<<1024, 256>>>(C, pi);
    cost_final_kernel<<<1, 256>>>(out);
}